// round 17
// baseline (speedup 1.0000x reference)
#include <cuda_runtime.h>

#define T_ 1024
#define B_ 512
#define I_ 128
#define H_ 256

#define NBR 8    // batch groups (independent barrier groups)
#define NHC 16   // h-column groups (16 h-cols per CTA)
#define HC  16
#define NCTA (NBR*NHC)   // 128

#define AROW_STRIDE 392   // padded a_sh row stride in floats (384 used), 16B-aligned
#define WPAIRS 192        // K pairs (K=384)
// smem floats: wIF4 12288 + wGO4 12288 + a_sh 12544 + bias4 64 + xch 1024
#define SMEM_FLOATS (WPAIRS*16*4*2 + 32*AROW_STRIDE + 16*4 + 32*16*2)
#define SMEM_BYTES (SMEM_FLOATS*4)

// ---------------- device globals ----------------
__device__ float    g_hbuf[2][B_*H_];
__device__ float    g_cbuf[B_*H_];
__device__ int      g_tstart[B_];
__device__ int      g_perm[B_];
__device__ int      g_cnt[T_];
__device__ int      g_tbegin;
__device__ unsigned g_barg[NBR];

// ---------------- tiny init (out = b_out, counters) ----------------
__global__ void k_zero(const float* __restrict__ bout, float* __restrict__ out) {
    int tid = threadIdx.x;  // 512
    out[tid] = bout[0];
    if (tid < NBR) g_barg[tid] = 0u;
    if (tid == 0) g_tbegin = T_ - 1;
}

// ---------------- per-row last-reset scan ----------------
__global__ void k_scan(const float* __restrict__ inp) {
    int b = blockIdx.x;
    int tid = threadIdx.x;  // 128
    int best = -1;
    for (int t = tid; t < T_ - 1; t += 128) {
        float v = inp[((size_t)t * B_ + b) * I_ + (I_ - 1)];
        if (v <= 0.0f) best = t;
    }
    __shared__ int red[128];
    red[tid] = best;
    __syncthreads();
    for (int off = 64; off; off >>= 1) {
        if (tid < off) red[tid] = max(red[tid], red[tid + off]);
        __syncthreads();
    }
    if (tid == 0) {
        int ts = red[0] + 1;
        g_tstart[b] = ts;
        atomicMin(&g_tbegin, ts);
    }
}

// ---------------- counting sort + prefix counts ----------------
__global__ void k_sortcnt() {
    __shared__ int hist[T_];
    __shared__ int bin[T_];
    __shared__ int wsum[32];
    int tid = threadIdx.x;  // 1024
    hist[tid] = 0;
    __syncthreads();
    if (tid < B_) atomicAdd(&hist[g_tstart[tid]], 1);
    __syncthreads();
    int v = hist[tid];
    int lane = tid & 31, w = tid >> 5;
    int x = v;
#pragma unroll
    for (int o = 1; o < 32; o <<= 1) {
        int y = __shfl_up_sync(0xffffffffu, x, o);
        if (lane >= o) x += y;
    }
    if (lane == 31) wsum[w] = x;
    __syncthreads();
    if (w == 0) {
        int y = wsum[lane];
#pragma unroll
        for (int o = 1; o < 32; o <<= 1) {
            int z = __shfl_up_sync(0xffffffffu, y, o);
            if (lane >= o) y += z;
        }
        wsum[lane] = y;
    }
    __syncthreads();
    int inc = x + (w ? wsum[w - 1] : 0);
    g_cnt[tid] = inc;
    bin[tid] = inc - v;
    __syncthreads();
    if (tid < B_) {
        int ts = g_tstart[tid];
        int pos = atomicAdd(&bin[ts], 1);
        g_perm[pos] = tid;
    }
}

__device__ __forceinline__ float sigf(float x) { return 1.0f / (1.0f + __expf(-x)); }

__device__ __forceinline__ void fma2(unsigned long long& acc, unsigned long long a,
                                     unsigned long long b) {
    asm("fma.rn.f32x2 %0, %1, %2, %0;" : "+l"(acc) : "l"(a), "l"(b));
}
__device__ __forceinline__ float unpack_sum(unsigned long long v) {
    float lo, hi;
    asm("mov.b64 {%0,%1}, %2;" : "=f"(lo), "=f"(hi) : "l"(v));
    return lo + hi;
}

// ---- one gate-half: NR rows (row = rw + 4q), lane = (hc, s2 K-half), 2 gates ----
// gh=1 warps ({g,o}) deposit sums in xch; gh=0 warps ({i,f}) keep sums in sA/sB.
template <int NR>
__device__ __forceinline__ void gate_half(
    const float* __restrict__ a_sh, const float4* __restrict__ warr,
    float2* __restrict__ xch, int rw, int hc, int s2, int gh,
    float* __restrict__ sA, float* __restrict__ sB)
{
    unsigned long long aA[NR], aB[NR];
#pragma unroll
    for (int q = 0; q < NR; ++q) { aA[q] = 0ull; aB[q] = 0ull; }

    const int P0 = s2 * 96;
#pragma unroll 2
    for (int p = P0; p < P0 + 96; p += 2) {
        ulonglong2 w0 = *(const ulonglong2*)&warr[(p    ) * 16 + hc];
        ulonglong2 w1 = *(const ulonglong2*)&warr[(p + 1) * 16 + hc];
#pragma unroll
        for (int q = 0; q < NR; ++q) {
            const ulonglong2 xx =
                *(const ulonglong2*)(a_sh + (rw + 4 * q) * AROW_STRIDE + 2 * p);
            fma2(aA[q], xx.x, w0.x); fma2(aB[q], xx.x, w0.y);
            fma2(aA[q], xx.y, w1.x); fma2(aB[q], xx.y, w1.y);
        }
    }

#pragma unroll
    for (int q = 0; q < NR; ++q) {
        float a = unpack_sum(aA[q]);
        float b = unpack_sum(aB[q]);
        a += __shfl_xor_sync(0xffffffffu, a, 16);   // combine K-halves
        b += __shfl_xor_sync(0xffffffffu, b, 16);
        if (gh) {
            if ((q & 1) == s2) xch[(rw + 4 * q) * 16 + hc] = make_float2(a, b);
        } else {
            sA[q] = a; sB[q] = b;
        }
    }
}

// ---------------- persistent group-synced recurrence ----------------
__global__ void __launch_bounds__(256, 1) k_lstm(
    const float* __restrict__ inp, const float* __restrict__ Wih,
    const float* __restrict__ Whh, const float* __restrict__ bih,
    const float* __restrict__ bhh, const float* __restrict__ Wout,
    float* __restrict__ out)
{
    extern __shared__ float sm[];
    float4* wIF4  = (float4*)sm;                          // [192*16]: (i0,i1,f0,f1)
    float4* wGO4  = wIF4 + WPAIRS * 16;                   // [192*16]: (g0,g1,o0,o1)
    float*  a_sh  = sm + WPAIRS * 16 * 4 * 2;             // [32][392]
    float4* bias4 = (float4*)(a_sh + 32 * AROW_STRIDE);   // [16]
    float2* xch   = (float2*)(bias4 + 16);                // [32*16] (g,o) exchange

    const int rgrp = blockIdx.x & (NBR - 1);
    const int j    = blockIdx.x >> 3;
    const int tid  = threadIdx.x;

    // ---- repack weight slice into SMEM as (pair, hc) x gate-pairs ----
    for (int idx = tid; idx < WPAIRS * 16; idx += 256) {
        int p = idx >> 4, hc0 = idx & 15;
        int ch = j * HC + hc0;
        int k0 = 2 * p;
        const float* Wsrc; int kk, ld;
        if (k0 < I_) { Wsrc = Wih; kk = k0;      ld = I_; }
        else         { Wsrc = Whh; kk = k0 - I_; ld = H_; }
        float2 iv = *(const float2*)&Wsrc[(0 * H_ + ch) * ld + kk];
        float2 fv = *(const float2*)&Wsrc[(1 * H_ + ch) * ld + kk];
        float2 gv = *(const float2*)&Wsrc[(2 * H_ + ch) * ld + kk];
        float2 ov = *(const float2*)&Wsrc[(3 * H_ + ch) * ld + kk];
        wIF4[idx] = make_float4(iv.x, iv.y, fv.x, fv.y);
        wGO4[idx] = make_float4(gv.x, gv.y, ov.x, ov.y);
    }
    if (tid < 16) {
        int ch = j * HC + tid;
        float4 bb;
        bb.x = bih[0 * H_ + ch] + bhh[0 * H_ + ch];
        bb.y = bih[1 * H_ + ch] + bhh[1 * H_ + ch];
        bb.z = bih[2 * H_ + ch] + bhh[2 * H_ + ch];
        bb.w = bih[3 * H_ + ch] + bhh[3 * H_ + ch];
        bias4[tid] = bb;
    }
    __syncthreads();

    const int warp = tid >> 5, lane = tid & 31;
    const int hc = lane & 15, s2 = lane >> 4;
    const int rw = warp >> 1, gh = warp & 1;
    const int col = j * HC + hc;
    const float4 myb = bias4[hc];
    const float wout_col = Wout[col];
    const float4* warr = gh ? wGO4 : wIF4;

    const int tb = g_tbegin;
    unsigned step = 0;

    for (int t = tb; t < T_; ++t) {
        const int n = g_cnt[t];
        const int n_prev = (t > 0) ? g_cnt[t - 1] : 0;
        const float* __restrict__ hread = g_hbuf[t & 1];
        float* __restrict__ hwrite = g_hbuf[(t + 1) & 1];
        const int mcount = (n > rgrp) ? ((n - rgrp + NBR - 1) >> 3) : 0;
        const bool last = (t == T_ - 1);

        for (int m0 = 0; m0 < mcount; m0 += 32) {
            const int chunk = min(32, mcount - m0);

            // ---- stage up to 32 active rows: [x_t(128) | h(256)] ----
            {
                int mm = tid >> 3, l8 = tid & 7;
                if (mm < chunk) {
                    int i = rgrp + (m0 + mm) * 8;
                    int b = g_perm[i];
                    const float4* xin = (const float4*)(inp + ((size_t)t * B_ + b) * I_);
                    float4* arow = (float4*)(a_sh + mm * AROW_STRIDE);
#pragma unroll
                    for (int q = 0; q < 4; ++q) arow[l8 + 8 * q] = xin[l8 + 8 * q];
                    if (i >= n_prev) {
                        float4 z = make_float4(0.f, 0.f, 0.f, 0.f);
#pragma unroll
                        for (int q = 0; q < 8; ++q) arow[32 + l8 + 8 * q] = z;
                    } else {
                        const float4* hin = (const float4*)(hread + b * H_);
#pragma unroll
                        for (int q = 0; q < 8; ++q) arow[32 + l8 + 8 * q] = hin[l8 + 8 * q];
                    }
                }
            }
            __syncthreads();

            const int avail = chunk - rw;       // rows rw + 4q
            float sA[8], sB[8];
            int nr = 0;
            if (avail > 0) {
                nr = ((avail - 1) >> 2) + 1;    // ceil(avail/4), <= 8
                switch (nr) {
                    case 1: gate_half<1>(a_sh, warr, xch, rw, hc, s2, gh, sA, sB); break;
                    case 2: gate_half<2>(a_sh, warr, xch, rw, hc, s2, gh, sA, sB); break;
                    case 3: gate_half<3>(a_sh, warr, xch, rw, hc, s2, gh, sA, sB); break;
                    case 4: gate_half<4>(a_sh, warr, xch, rw, hc, s2, gh, sA, sB); break;
                    case 5: gate_half<5>(a_sh, warr, xch, rw, hc, s2, gh, sA, sB); break;
                    case 6: gate_half<6>(a_sh, warr, xch, rw, hc, s2, gh, sA, sB); break;
                    case 7: gate_half<7>(a_sh, warr, xch, rw, hc, s2, gh, sA, sB); break;
                    default: gate_half<8>(a_sh, warr, xch, rw, hc, s2, gh, sA, sB); break;
                }
            }
            __syncthreads();   // xch visible; a_sh free for next staging

            // ---- epilogue on gh=0 warps (have i,f; read g,o from xch) ----
            if (gh == 0 && nr > 0) {
                const unsigned hmask = s2 ? 0xffff0000u : 0x0000ffffu;
#pragma unroll
                for (int q = 0; q < 8; ++q) {
                    if (q < nr && (q & 1) == s2) {
                        int mrow = rw + 4 * q;
                        int i = rgrp + (m0 + mrow) * 8;
                        int b = g_perm[i];
                        float2 go = xch[mrow * 16 + hc];
                        float gi = sigf(sA[q] + myb.x);
                        float gf = sigf(sB[q] + myb.y);
                        float gg = tanhf(go.x + myb.z);
                        float oo = sigf(go.y + myb.w);
                        float c  = (i >= n_prev) ? 0.0f : g_cbuf[b * H_ + col];
                        float cn = gf * c + gi * gg;
                        float hn = oo * tanhf(cn);
                        if (!last) {
                            g_cbuf[b * H_ + col]  = cn;
                            hwrite[b * H_ + col]  = hn;
                        } else {
                            float vv = hn * wout_col;
                            vv += __shfl_xor_sync(hmask, vv, 8);
                            vv += __shfl_xor_sync(hmask, vv, 4);
                            vv += __shfl_xor_sync(hmask, vv, 2);
                            vv += __shfl_xor_sync(hmask, vv, 1);
                            if (hc == 0) atomicAdd(&out[b], vv);
                        }
                    }
                }
            }
        }

        if (last) break;

        // ---- per-r-group software barrier (16 CTAs) ----
        step++;
        __syncthreads();
        if (tid == 0) {
            __threadfence();
            atomicAdd(&g_barg[rgrp], 1u);
            unsigned target = step * (unsigned)NHC;
            unsigned v;
            do {
                asm volatile("ld.acquire.gpu.u32 %0, [%1];" : "=r"(v) : "l"(&g_barg[rgrp]) : "memory");
            } while (v < target);
        }
        __syncthreads();
    }
}

extern "C" void kernel_launch(void* const* d_in, const int* in_sizes, int n_in,
                              void* d_out, int out_size) {
    (void)in_sizes; (void)n_in; (void)out_size;
    const float* inp  = (const float*)d_in[0];
    const float* Wih  = (const float*)d_in[1];
    const float* Whh  = (const float*)d_in[2];
    const float* bih  = (const float*)d_in[3];
    const float* bhh  = (const float*)d_in[4];
    const float* Wout = (const float*)d_in[5];
    const float* bout = (const float*)d_in[6];
    float* out = (float*)d_out;

    cudaFuncSetAttribute(k_lstm, cudaFuncAttributeMaxDynamicSharedMemorySize, SMEM_BYTES);

    k_zero<<<1, 512>>>(bout, out);
    k_scan<<<B_, 128>>>(inp);
    k_sortcnt<<<1, 1024>>>();
    k_lstm<<<NCTA, 256, SMEM_BYTES>>>(inp, Wih, Whh, bih, bhh, Wout, out);
}